// round 1
// baseline (speedup 1.0000x reference)
#include <cuda_runtime.h>
#include <math.h>

// Problem constants
#define NB 4
#define NN 4096
#define NE 32768        // edges per graph (dedup: batch tiling is degenerate)
#define AC 16
#define UC 16
#define INC 32
#define OUTC 32
#define HID 8

// Scratch (device globals; no allocation allowed)
__device__ int   g_src[NE];
__device__ int   g_dst[NE];
__device__ float g_p1[NN * HID];      // w1[:, :34] @ pw[n]
__device__ float g_p2[NN * HID];      // w1[:, 34:] @ pw[n]
__device__ float g_T [NN * HID * OUTC]; // T[n][k][o] = sum_i x0[n,i]*w2[(i*32+o)*8+k]  (4 MB)
__device__ float g_c [NN * OUTC];     // c[n][o]   = sum_i x0[n,i]*b2[i*32+o]
__device__ float g_agg[NN * OUTC];
__device__ float g_cnt[NN];

// ---------------------------------------------------------------------------
// K0: zero accumulators + decode edge indices (int32/int64 auto-detect)
// ---------------------------------------------------------------------------
__global__ void k_init(const int* __restrict__ ew) {
    int t = blockIdx.x * blockDim.x + threadIdx.x;
    if (t < NN * OUTC) g_agg[t] = 0.f;
    if (t < NN)        g_cnt[t] = 0.f;
    if (t < NE) {
        // If buffer is int64, every odd 32-bit word is the high word of a
        // value in [0,4096) -> 0. If int32, odd words are random indices.
        bool is64 = true;
        #pragma unroll
        for (int s = 1; s <= 31; s += 2) is64 = is64 && (ew[s] == 0);
        if (is64) {
            g_src[t] = ew[2 * t];
            g_dst[t] = ew[2 * NE + 2 * t];
        } else {
            g_src[t] = ew[t];
            g_dst[t] = ew[NE + t];
        }
    }
}

// ---------------------------------------------------------------------------
// K1: per-node layer-1 projections p1, p2 (pw = [a(16), u(16), grid(2)])
// one thread per (node, k) : 4096*8 threads
// ---------------------------------------------------------------------------
__global__ void k_node(const float* __restrict__ a, const float* __restrict__ u,
                       const float* __restrict__ grid, const float* __restrict__ w1) {
    int t = blockIdx.x * blockDim.x + threadIdx.x;
    if (t >= NN * HID) return;
    int n = t >> 3, k = t & 7;
    const float* r = w1 + k * 68;   // w1 row k: [0:34) src half, [34:68) dst half
    float s1 = 0.f, s2 = 0.f;
    #pragma unroll
    for (int j = 0; j < 16; j++) {
        float v = __ldg(&a[j * NN + n]);
        s1 += r[j]      * v;
        s2 += r[34 + j] * v;
    }
    #pragma unroll
    for (int j = 0; j < 16; j++) {
        float v = __ldg(&u[j * NN + n]);
        s1 += r[16 + j] * v;
        s2 += r[50 + j] * v;
    }
    float gg0 = __ldg(&grid[2 * n]), gg1 = __ldg(&grid[2 * n + 1]);
    s1 += r[32] * gg0 + r[33] * gg1;
    s2 += r[66] * gg0 + r[67] * gg1;
    g_p1[t] = s1;
    g_p2[t] = s2;
}

// ---------------------------------------------------------------------------
// K2: T = X0 @ W2r  (4096 x 32 x 256 GEMM) and c = X0 @ B2r
// 128 blocks x 256 threads, 32 nodes per block
// T[n][k*32+o] = sum_i x0[n,i] * w2[(i*32+o)*8 + k]
// ---------------------------------------------------------------------------
__global__ void k_T(const float* __restrict__ a, const float* __restrict__ u,
                    const float* __restrict__ w2, const float* __restrict__ b2) {
    __shared__ float xs[32][33];
    __shared__ float w2s[32][256];
    int tid = threadIdx.x;
    int nb  = blockIdx.x * 32;

    // load W2r into shared: w2s[i][c0], c0 = k*32+o
    for (int idx = tid; idx < 32 * 256; idx += 256) {
        int i = idx >> 8, c0 = idx & 255;
        w2s[i][c0] = w2[(i * 32 + (c0 & 31)) * 8 + (c0 >> 5)];
    }
    // load X0 tile (32 nodes x 32 ch), coalesced over n
    for (int idx = tid; idx < 32 * 32; idx += 256) {
        int i = idx >> 5, nl = idx & 31;
        int n = nb + nl;
        xs[nl][i] = (i < 16) ? a[i * NN + n] : u[(i - 16) * NN + n];
    }
    __syncthreads();

    float acc[32];
    #pragma unroll
    for (int ln = 0; ln < 32; ln++) acc[ln] = 0.f;
    int c0 = tid;
    #pragma unroll 8
    for (int i = 0; i < 32; i++) {
        float w = w2s[i][c0];
        #pragma unroll
        for (int ln = 0; ln < 32; ln++) acc[ln] += xs[ln][i] * w;
    }
    #pragma unroll
    for (int ln = 0; ln < 32; ln++)
        g_T[(nb + ln) * 256 + c0] = acc[ln];   // coalesced across threads

    // c[n][o] = sum_i x0[n,i]*b2[i*32+o]  (b2 is zeros in setup; computed anyway)
    if (tid < 32) {
        int o = tid;
        for (int ln = 0; ln < 32; ln++) {
            float cc = 0.f;
            #pragma unroll
            for (int i = 0; i < 32; i++) cc += xs[ln][i] * b2[i * 32 + o];
            g_c[(nb + ln) * 32 + o] = cc;
        }
    }
}

// ---------------------------------------------------------------------------
// K3: warp-per-edge message + scatter. h = gelu(p1[src]+p2[dst]+b1),
// msg[o] = c[src][o] + sum_k h[k]*T[src][k][o], atomicAdd to agg[dst]
// ---------------------------------------------------------------------------
__global__ void k_edge(const float* __restrict__ b1) {
    int gw   = (blockIdx.x * blockDim.x + threadIdx.x) >> 5;
    int lane = threadIdx.x & 31;
    if (gw >= NE) return;
    int src = g_src[gw];
    int dst = g_dst[gw];

    // lanes 0..7 compute gelu once, broadcast via shuffle
    float hv = 0.f;
    if (lane < 8) {
        float x = g_p1[src * 8 + lane] + g_p2[dst * 8 + lane] + __ldg(&b1[lane]);
        hv = 0.5f * x * (1.0f + erff(x * 0.70710678118654752f));
    }
    float h[8];
    #pragma unroll
    for (int k = 0; k < 8; k++) h[k] = __shfl_sync(0xffffffffu, hv, k);

    float m = g_c[src * 32 + lane];
    const float* Tp = g_T + src * 256 + lane;
    #pragma unroll
    for (int k = 0; k < 8; k++) m += h[k] * Tp[k * 32];   // coalesced 128B rows

    atomicAdd(&g_agg[dst * 32 + lane], m);
    if (lane == 0) atomicAdd(&g_cnt[dst], 1.0f);
}

// ---------------------------------------------------------------------------
// K4: out[b,o,n] = (b==0 ? agg[n,o]/max(cnt,1) : 0) + sum_i x[b,n,i]*root[i,o]
// block = 64 nodes for one batch; coalesced writes along n
// ---------------------------------------------------------------------------
__global__ void k_out(const float* __restrict__ a, const float* __restrict__ u,
                      const float* __restrict__ root, float* __restrict__ out) {
    __shared__ float xs[64][33];
    __shared__ float rs[32][32];
    int tid = threadIdx.x;
    int b   = blockIdx.y;
    int nb  = blockIdx.x * 64;

    for (int idx = tid; idx < 32 * 32; idx += 256)
        rs[idx >> 5][idx & 31] = root[idx];
    for (int idx = tid; idx < 64 * 32; idx += 256) {
        int i = idx >> 6, nl = idx & 63;
        int n = nb + nl;
        xs[nl][i] = (i < 16) ? a[(b * 16 + i) * NN + n]
                             : u[(b * 16 + (i - 16)) * NN + n];
    }
    __syncthreads();

    int og = tid >> 6;          // 0..3 -> 8 o's each
    int nl = tid & 63;
    int n  = nb + nl;
    float inv = 0.f;
    if (b == 0) inv = 1.0f / fmaxf(g_cnt[n], 1.0f);

    #pragma unroll
    for (int oo = 0; oo < 8; oo++) {
        int o = og * 8 + oo;
        float v = 0.f;
        #pragma unroll
        for (int i = 0; i < 32; i++) v += xs[nl][i] * rs[i][o];
        if (b == 0) v += g_agg[n * 32 + o] * inv;
        out[(b * OUTC + o) * NN + n] = v;   // coalesced over nl
    }
}

// ---------------------------------------------------------------------------
extern "C" void kernel_launch(void* const* d_in, const int* in_sizes, int n_in,
                              void* d_out, int out_size) {
    const float* a    = (const float*)d_in[0];
    const float* u    = (const float*)d_in[1];
    const float* grid = (const float*)d_in[2];
    const int*   ew   = (const int*)  d_in[3];   // int32 or int64 (auto-detected)
    const float* w1   = (const float*)d_in[4];
    const float* b1   = (const float*)d_in[5];
    const float* w2   = (const float*)d_in[6];
    const float* b2   = (const float*)d_in[7];
    const float* root = (const float*)d_in[8];
    float* out = (float*)d_out;

    k_init<<<(NN * OUTC + 255) / 256, 256>>>(ew);
    k_node<<<(NN * HID + 255) / 256, 256>>>(a, u, grid, w1);
    k_T   <<<NN / 32, 256>>>(a, u, w2, b2);
    k_edge<<<(NE * 32) / 256, 256>>>(b1);
    k_out <<<dim3(NN / 64, NB), 256>>>(a, u, root, out);
}

// round 2
// speedup vs baseline: 1.1480x; 1.1480x over previous
#include <cuda_runtime.h>
#include <math.h>

#define NB 4
#define NN 4096
#define NE 32768
#define OUTC 32
#define HID 8

// Scratch (device globals)
__device__ int   g_src[NE];
__device__ int   g_dst[NE];
__device__ float g_p1[NN * HID];
__device__ float g_p2[NN * HID];
__device__ float g_T [NN * HID * OUTC];   // layout: T[n][o*8+k]  (4 MB)
__device__ float g_c [NN * OUTC];
__device__ float g_agg[NN * OUTC];
__device__ float g_cnt[NN];

// ---------------------------------------------------------------------------
// Fused prep kernel, 448 blocks x 256 threads, three roles:
//   blocks [0,128):   T = X0 @ W2r (per-node 8x32 factor, layout [n][o*8+k]) + c
//   blocks [128,256): node projections p1/p2 + zero agg/cnt + edge decode
//   blocks [256,448): output rows for batches 1..3 (root term only, no agg)
// ---------------------------------------------------------------------------
__global__ void k_prep(const float* __restrict__ a, const float* __restrict__ u,
                       const float* __restrict__ grid, const int* __restrict__ ew,
                       const float* __restrict__ w1, const float* __restrict__ w2,
                       const float* __restrict__ b2, const float* __restrict__ root,
                       float* __restrict__ out) {
    __shared__ union {
        struct { float xs[32][33]; float w2s[32][256]; } t;   // role A
        struct { float xs[64][33]; float rs[32][32];   } o;   // role C
    } sm;
    int tid = threadIdx.x;
    int bid = blockIdx.x;

    if (bid < 128) {
        // ---------------- role A: T factor GEMM ----------------
        int nb = bid * 32;
        // W2 reshaped: w2s[i][c0] = w2[i*256 + c0], c0 = o*8+k  (contiguous copy)
        for (int idx = tid; idx < 32 * 256; idx += 256) {
            int i = idx >> 8, c0 = idx & 255;
            sm.t.w2s[i][c0] = w2[i * 256 + c0];
        }
        for (int idx = tid; idx < 32 * 32; idx += 256) {
            int i = idx >> 5, nl = idx & 31;
            int n = nb + nl;
            sm.t.xs[nl][i] = (i < 16) ? a[i * NN + n] : u[(i - 16) * NN + n];
        }
        __syncthreads();

        float acc[32];
        #pragma unroll
        for (int ln = 0; ln < 32; ln++) acc[ln] = 0.f;
        int c0 = tid;
        #pragma unroll 8
        for (int i = 0; i < 32; i++) {
            float w = sm.t.w2s[i][c0];
            #pragma unroll
            for (int ln = 0; ln < 32; ln++) acc[ln] += sm.t.xs[ln][i] * w;
        }
        #pragma unroll
        for (int ln = 0; ln < 32; ln++)
            g_T[(nb + ln) * 256 + c0] = acc[ln];

        if (tid < 32) {                       // c[n][o] (b2 is zeros, kept exact)
            int o = tid;
            for (int ln = 0; ln < 32; ln++) {
                float cc = 0.f;
                #pragma unroll
                for (int i = 0; i < 32; i++) cc += sm.t.xs[ln][i] * b2[i * 32 + o];
                g_c[(nb + ln) * 32 + o] = cc;
            }
        }
    } else if (bid < 256) {
        // ---------------- role B: node proj + init + edge decode ----------------
        int t = (bid - 128) * 256 + tid;      // t in [0, 32768)
        int n = t >> 3, k = t & 7;
        const float* r = w1 + k * 68;
        float s1 = 0.f, s2 = 0.f;
        #pragma unroll
        for (int j = 0; j < 16; j++) {
            float v = __ldg(&a[j * NN + n]);
            s1 += r[j]      * v;
            s2 += r[34 + j] * v;
        }
        #pragma unroll
        for (int j = 0; j < 16; j++) {
            float v = __ldg(&u[j * NN + n]);
            s1 += r[16 + j] * v;
            s2 += r[50 + j] * v;
        }
        float gg0 = __ldg(&grid[2 * n]), gg1 = __ldg(&grid[2 * n + 1]);
        s1 += r[32] * gg0 + r[33] * gg1;
        s2 += r[66] * gg0 + r[67] * gg1;
        g_p1[t] = s1;
        g_p2[t] = s2;

        ((float4*)g_agg)[t] = make_float4(0.f, 0.f, 0.f, 0.f);
        if (t < NN) g_cnt[t] = 0.f;

        // edge decode (int64 vs int32 auto-detect: int64 values < 4096 -> high words 0)
        bool is64 = true;
        #pragma unroll
        for (int s = 1; s <= 31; s += 2) is64 = is64 && (ew[s] == 0);
        if (is64) {
            g_src[t] = ew[2 * t];
            g_dst[t] = ew[2 * NE + 2 * t];
        } else {
            g_src[t] = ew[t];
            g_dst[t] = ew[NE + t];
        }
    } else {
        // ---------------- role C: out rows for b = 1..3 (root term only) ----------------
        int bid2 = bid - 256;
        int b  = 1 + (bid2 >> 6);
        int nb = (bid2 & 63) * 64;
        for (int idx = tid; idx < 32 * 32; idx += 256)
            sm.o.rs[idx >> 5][idx & 31] = root[idx];
        for (int idx = tid; idx < 64 * 32; idx += 256) {
            int i = idx >> 6, nl = idx & 63;
            int n = nb + nl;
            sm.o.xs[nl][i] = (i < 16) ? a[(b * 16 + i) * NN + n]
                                      : u[(b * 16 + (i - 16)) * NN + n];
        }
        __syncthreads();
        int og = tid >> 6, nl = tid & 63, n = nb + nl;
        #pragma unroll
        for (int oo = 0; oo < 8; oo++) {
            int o = og * 8 + oo;
            float v = 0.f;
            #pragma unroll
            for (int i = 0; i < 32; i++) v += sm.o.xs[nl][i] * sm.o.rs[i][o];
            out[(b * OUTC + o) * NN + n] = v;
        }
    }
}

// ---------------------------------------------------------------------------
// Edge kernel: warp per edge. h = gelu(p1[src]+p2[dst]+b1);
// msg[o] = c[src][o] + sum_k h[k]*T[src][o*8+k]  -> two LDG.128 per lane.
// ---------------------------------------------------------------------------
__global__ void k_edge(const float* __restrict__ b1) {
    int gw   = (blockIdx.x * blockDim.x + threadIdx.x) >> 5;
    int lane = threadIdx.x & 31;
    int src = g_src[gw];
    int dst = g_dst[gw];

    float hv = 0.f;
    if (lane < 8) {
        float x = g_p1[src * 8 + lane] + g_p2[dst * 8 + lane] + __ldg(&b1[lane]);
        hv = 0.5f * x * (1.0f + erff(x * 0.70710678118654752f));
    }
    float h[8];
    #pragma unroll
    for (int k = 0; k < 8; k++) h[k] = __shfl_sync(0xffffffffu, hv, k);

    const float4* Tp = (const float4*)(g_T + src * 256 + lane * 8);
    float4 t0 = Tp[0];
    float4 t1 = Tp[1];
    float m = g_c[src * 32 + lane]
            + h[0] * t0.x + h[1] * t0.y + h[2] * t0.z + h[3] * t0.w
            + h[4] * t1.x + h[5] * t1.y + h[6] * t1.z + h[7] * t1.w;

    atomicAdd(&g_agg[dst * 32 + lane], m);
    if (lane == 0) atomicAdd(&g_cnt[dst], 1.0f);
}

// ---------------------------------------------------------------------------
// Final kernel: batch-0 output (root term + agg/cnt). 64 blocks.
// ---------------------------------------------------------------------------
__global__ void k_out0(const float* __restrict__ a, const float* __restrict__ u,
                       const float* __restrict__ root, float* __restrict__ out) {
    __shared__ float xs[64][33];
    __shared__ float rs[32][32];
    int tid = threadIdx.x;
    int nb  = blockIdx.x * 64;

    for (int idx = tid; idx < 32 * 32; idx += 256)
        rs[idx >> 5][idx & 31] = root[idx];
    for (int idx = tid; idx < 64 * 32; idx += 256) {
        int i = idx >> 6, nl = idx & 63;
        int n = nb + nl;
        xs[nl][i] = (i < 16) ? a[i * NN + n] : u[(i - 16) * NN + n];
    }
    __syncthreads();

    int og = tid >> 6, nl = tid & 63, n = nb + nl;
    float inv = 1.0f / fmaxf(g_cnt[n], 1.0f);

    #pragma unroll
    for (int oo = 0; oo < 8; oo++) {
        int o = og * 8 + oo;
        float v = 0.f;
        #pragma unroll
        for (int i = 0; i < 32; i++) v += xs[nl][i] * rs[i][o];
        v += g_agg[n * 32 + o] * inv;
        out[o * NN + n] = v;
    }
}

// ---------------------------------------------------------------------------
extern "C" void kernel_launch(void* const* d_in, const int* in_sizes, int n_in,
                              void* d_out, int out_size) {
    const float* a    = (const float*)d_in[0];
    const float* u    = (const float*)d_in[1];
    const float* grid = (const float*)d_in[2];
    const int*   ew   = (const int*)  d_in[3];
    const float* w1   = (const float*)d_in[4];
    const float* b1   = (const float*)d_in[5];
    const float* w2   = (const float*)d_in[6];
    const float* b2   = (const float*)d_in[7];
    const float* root = (const float*)d_in[8];
    float* out = (float*)d_out;

    k_prep<<<448, 256>>>(a, u, grid, ew, w1, w2, b2, root, out);
    k_edge<<<(NE * 32) / 256, 256>>>(b1);
    k_out0<<<64, 256>>>(a, u, root, out);
}

// round 3
// speedup vs baseline: 1.2361x; 1.0767x over previous
#include <cuda_runtime.h>
#include <math.h>

#define NB 4
#define NN 4096
#define NE 32768
#define OUTC 32
#define HID 8

// Scratch (device globals)
__device__ int   g_src[NE];
__device__ int   g_dst[NE];
__device__ float g_p1[NN * HID];
__device__ float g_p2[NN * HID];
__device__ float g_T [NN * HID * OUTC];   // layout: T[n][o*8+k]  (4 MB)
__device__ float g_c [NN * OUTC];
__device__ float g_agg[NN * OUTC];
__device__ float g_cnt[NN];

// Role block ranges
#define RA_END 512              // T GEMM: 8 nodes/block
#define RB_END (RA_END + 16)    // node proj: 256 nodes/block
#define RC_END (RB_END + 192)   // out b=1..3: 64 nodes/block
#define RD_END (RC_END + 128)   // init + edge decode: 256 edges/block

// ---------------------------------------------------------------------------
// Fused prep kernel: 848 independent blocks, 4 roles, no cross-role deps.
// ---------------------------------------------------------------------------
__global__ void k_prep(const float* __restrict__ a, const float* __restrict__ u,
                       const float* __restrict__ grid, const int* __restrict__ ew,
                       const float* __restrict__ w1, const float* __restrict__ w2,
                       const float* __restrict__ b2, const float* __restrict__ root,
                       float* __restrict__ out) {
    __shared__ union {
        float xa[8][33];                               // role A
        float ws[HID * 68];                            // role B
        struct { float xs[64][33]; float rs[32][32]; } o; // role C
    } sm;
    int tid = threadIdx.x;
    int bid = blockIdx.x;

    if (bid < RA_END) {
        // ---- role A: T[n][c0] = sum_i x0[n,i] * w2[i*256+c0], 8 nodes/block ----
        int nb = bid * 8;
        {
            int i = tid >> 3, nl = tid & 7;
            int n = nb + nl;
            sm.xa[nl][i] = (i < 16) ? a[i * NN + n] : u[(i - 16) * NN + n];
        }
        __syncthreads();

        int c0 = tid;
        float acc[8];
        #pragma unroll
        for (int nl = 0; nl < 8; nl++) acc[nl] = 0.f;
        #pragma unroll 8
        for (int i = 0; i < 32; i++) {
            float w = __ldg(&w2[i * 256 + c0]);        // coalesced; w2 L1-resident
            #pragma unroll
            for (int nl = 0; nl < 8; nl++) acc[nl] += sm.xa[nl][i] * w;
        }
        #pragma unroll
        for (int nl = 0; nl < 8; nl++)
            g_T[(nb + nl) * 256 + c0] = acc[nl];       // coalesced

        if (tid < 32) {                                // c[n][o] (exactness: b2 may be nonzero)
            int o = tid;
            #pragma unroll
            for (int nl = 0; nl < 8; nl++) {
                float cc = 0.f;
                #pragma unroll
                for (int i = 0; i < 32; i++) cc += sm.xa[nl][i] * __ldg(&b2[i * 32 + o]);
                g_c[(nb + nl) * 32 + o] = cc;
            }
        }
    } else if (bid < RB_END) {
        // ---- role B: node projections, one thread per node (coalesced) ----
        for (int idx = tid; idx < HID * 68; idx += 256) sm.ws[idx] = w1[idx];
        __syncthreads();
        int n = (bid - RA_END) * 256 + tid;

        float s1[8], s2[8];
        #pragma unroll
        for (int k = 0; k < 8; k++) { s1[k] = 0.f; s2[k] = 0.f; }
        #pragma unroll
        for (int j = 0; j < 16; j++) {
            float v = a[j * NN + n];                   // coalesced over tid
            #pragma unroll
            for (int k = 0; k < 8; k++) {
                s1[k] += sm.ws[k * 68 + j]      * v;
                s2[k] += sm.ws[k * 68 + 34 + j] * v;
            }
        }
        #pragma unroll
        for (int j = 0; j < 16; j++) {
            float v = u[j * NN + n];
            #pragma unroll
            for (int k = 0; k < 8; k++) {
                s1[k] += sm.ws[k * 68 + 16 + j] * v;
                s2[k] += sm.ws[k * 68 + 50 + j] * v;
            }
        }
        float g0 = grid[2 * n], g1 = grid[2 * n + 1];
        #pragma unroll
        for (int k = 0; k < 8; k++) {
            s1[k] += sm.ws[k * 68 + 32] * g0 + sm.ws[k * 68 + 33] * g1;
            s2[k] += sm.ws[k * 68 + 66] * g0 + sm.ws[k * 68 + 67] * g1;
        }
        float4* p1v = (float4*)(g_p1 + n * 8);
        float4* p2v = (float4*)(g_p2 + n * 8);
        p1v[0] = make_float4(s1[0], s1[1], s1[2], s1[3]);
        p1v[1] = make_float4(s1[4], s1[5], s1[6], s1[7]);
        p2v[0] = make_float4(s2[0], s2[1], s2[2], s2[3]);
        p2v[1] = make_float4(s2[4], s2[5], s2[6], s2[7]);
    } else if (bid < RC_END) {
        // ---- role C: out rows for b = 1..3 (root term only) ----
        int bid2 = bid - RB_END;
        int b  = 1 + (bid2 >> 6);
        int nb = (bid2 & 63) * 64;
        for (int idx = tid; idx < 32 * 32; idx += 256)
            sm.o.rs[idx >> 5][idx & 31] = root[idx];
        for (int idx = tid; idx < 64 * 32; idx += 256) {
            int i = idx >> 6, nl = idx & 63;
            int n = nb + nl;
            sm.o.xs[nl][i] = (i < 16) ? a[(b * 16 + i) * NN + n]
                                      : u[(b * 16 + (i - 16)) * NN + n];
        }
        __syncthreads();
        int og = tid >> 6, nl = tid & 63, n = nb + nl;
        #pragma unroll
        for (int oo = 0; oo < 8; oo++) {
            int o = og * 8 + oo;
            float v = 0.f;
            #pragma unroll
            for (int i = 0; i < 32; i++) v += sm.o.xs[nl][i] * sm.o.rs[i][o];
            out[(b * OUTC + o) * NN + n] = v;
        }
    } else {
        // ---- role D: zero accumulators + edge decode ----
        int t = (bid - RC_END) * 256 + tid;            // [0, 32768)
        ((float4*)g_agg)[t] = make_float4(0.f, 0.f, 0.f, 0.f);
        if (t < NN) g_cnt[t] = 0.f;

        bool is64 = true;                              // int64 idx < 4096 -> odd words 0
        #pragma unroll
        for (int s = 1; s <= 31; s += 2) is64 = is64 && (ew[s] == 0);
        if (is64) {
            g_src[t] = ew[2 * t];
            g_dst[t] = ew[2 * NE + 2 * t];
        } else {
            g_src[t] = ew[t];
            g_dst[t] = ew[NE + t];
        }
    }
}

// ---------------------------------------------------------------------------
// Edge kernel: warp per edge. h = gelu(p1[src]+p2[dst]+b1);
// msg[o] = c[src][o] + sum_k h[k]*T[src][o*8+k]  (two LDG.128 per lane)
// ---------------------------------------------------------------------------
__global__ void k_edge(const float* __restrict__ b1) {
    int gw   = (blockIdx.x * blockDim.x + threadIdx.x) >> 5;
    int lane = threadIdx.x & 31;
    int src = g_src[gw];
    int dst = g_dst[gw];

    float hv = 0.f;
    if (lane < 8) {
        float x = g_p1[src * 8 + lane] + g_p2[dst * 8 + lane] + __ldg(&b1[lane]);
        hv = 0.5f * x * (1.0f + erff(x * 0.70710678118654752f));
    }
    float h[8];
    #pragma unroll
    for (int k = 0; k < 8; k++) h[k] = __shfl_sync(0xffffffffu, hv, k);

    const float4* Tp = (const float4*)(g_T + src * 256 + lane * 8);
    float4 t0 = Tp[0];
    float4 t1 = Tp[1];
    float m = g_c[src * 32 + lane]
            + h[0] * t0.x + h[1] * t0.y + h[2] * t0.z + h[3] * t0.w
            + h[4] * t1.x + h[5] * t1.y + h[6] * t1.z + h[7] * t1.w;

    atomicAdd(&g_agg[dst * 32 + lane], m);
    if (lane == 0) atomicAdd(&g_cnt[dst], 1.0f);
}

// ---------------------------------------------------------------------------
// Final kernel: batch-0 output (root term + agg/cnt). 64 blocks.
// ---------------------------------------------------------------------------
__global__ void k_out0(const float* __restrict__ a, const float* __restrict__ u,
                       const float* __restrict__ root, float* __restrict__ out) {
    __shared__ float xs[64][33];
    __shared__ float rs[32][32];
    int tid = threadIdx.x;
    int nb  = blockIdx.x * 64;

    for (int idx = tid; idx < 32 * 32; idx += 256)
        rs[idx >> 5][idx & 31] = root[idx];
    for (int idx = tid; idx < 64 * 32; idx += 256) {
        int i = idx >> 6, nl = idx & 63;
        int n = nb + nl;
        xs[nl][i] = (i < 16) ? a[i * NN + n] : u[(i - 16) * NN + n];
    }
    __syncthreads();

    int og = tid >> 6, nl = tid & 63, n = nb + nl;
    float inv = 1.0f / fmaxf(g_cnt[n], 1.0f);

    #pragma unroll
    for (int oo = 0; oo < 8; oo++) {
        int o = og * 8 + oo;
        float v = 0.f;
        #pragma unroll
        for (int i = 0; i < 32; i++) v += xs[nl][i] * rs[i][o];
        v += g_agg[n * 32 + o] * inv;
        out[o * NN + n] = v;
    }
}

// ---------------------------------------------------------------------------
extern "C" void kernel_launch(void* const* d_in, const int* in_sizes, int n_in,
                              void* d_out, int out_size) {
    const float* a    = (const float*)d_in[0];
    const float* u    = (const float*)d_in[1];
    const float* grid = (const float*)d_in[2];
    const int*   ew   = (const int*)  d_in[3];
    const float* w1   = (const float*)d_in[4];
    const float* b1   = (const float*)d_in[5];
    const float* w2   = (const float*)d_in[6];
    const float* b2   = (const float*)d_in[7];
    const float* root = (const float*)d_in[8];
    float* out = (float*)d_out;

    k_prep<<<RD_END, 256>>>(a, u, grid, ew, w1, w2, b2, root, out);
    k_edge<<<(NE * 32) / 256, 256>>>(b1);
    k_out0<<<64, 256>>>(a, u, root, out);
}

// round 4
// speedup vs baseline: 1.3236x; 1.0708x over previous
#include <cuda_runtime.h>
#include <math.h>

#define NB 4
#define NN 4096
#define NE 32768
#define OUTC 32
#define HID 8

// Scratch (device globals)
__device__ int   g_src[NE];
__device__ int   g_dst[NE];
__device__ float g_p1[NN * HID];
__device__ float g_p2[NN * HID];
__device__ float g_T [NN * HID * OUTC];   // layout: T[n][o*8+k]  (4 MB)
__device__ float g_c [NN * OUTC];
__device__ float g_agg[NN * OUTC];
__device__ float g_cnt[NN];

// Role block ranges
#define RA_END 512               // T GEMM: 8 nodes/block
#define RB_END (RA_END + 32)     // node proj: 128 nodes/block, 2 thr/node
#define RC_END (RB_END + 192)    // out b=1..3: 64 nodes/block
#define RD_END (RC_END + 128)    // init + edge decode: 256 edges/block

// ---------------------------------------------------------------------------
// Fused prep kernel: 864 independent blocks, 4 roles.
// __launch_bounds__(256,4): 64-reg ceiling -> 4 blocks/SM -> ~50% occ.
// ---------------------------------------------------------------------------
__global__ void __launch_bounds__(256, 4)
k_prep(const float* __restrict__ a, const float* __restrict__ u,
       const float* __restrict__ grid, const int* __restrict__ ew,
       const float* __restrict__ w1, const float* __restrict__ w2,
       const float* __restrict__ b2, const float* __restrict__ root,
       float* __restrict__ out) {
    __shared__ union {
        float xa[8][33];                                  // role A
        float ws[HID * 68];                               // role B
        struct { float xs[64][33]; float rs[32][32]; } o; // role C
    } sm;
    int tid = threadIdx.x;
    int bid = blockIdx.x;

    if (bid < RA_END) {
        // ---- role A: T[n][c0] = sum_i x0[n,i] * w2[i*256+c0], 8 nodes/block ----
        int nb = bid * 8;
        {
            int i = tid >> 3, nl = tid & 7;
            int n = nb + nl;
            sm.xa[nl][i] = (i < 16) ? a[i * NN + n] : u[(i - 16) * NN + n];
        }
        __syncthreads();

        int c0 = tid;
        float acc[8];
        #pragma unroll
        for (int nl = 0; nl < 8; nl++) acc[nl] = 0.f;
        #pragma unroll 4
        for (int i = 0; i < 32; i++) {
            float w = __ldg(&w2[i * 256 + c0]);           // coalesced
            #pragma unroll
            for (int nl = 0; nl < 8; nl++) acc[nl] += sm.xa[nl][i] * w;
        }
        #pragma unroll
        for (int nl = 0; nl < 8; nl++)
            g_T[(nb + nl) * 256 + c0] = acc[nl];          // coalesced

        if (tid < 32) {                                   // c[n][o]
            int o = tid;
            #pragma unroll
            for (int nl = 0; nl < 8; nl++) {
                float cc = 0.f;
                #pragma unroll
                for (int i = 0; i < 32; i++) cc += sm.xa[nl][i] * __ldg(&b2[i * 32 + o]);
                g_c[(nb + nl) * 32 + o] = cc;
            }
        }
    } else if (bid < RB_END) {
        // ---- role B: node projections, 2 threads/node (half=0 -> p1, half=1 -> p2) ----
        for (int idx = tid; idx < HID * 68; idx += 256) sm.ws[idx] = w1[idx];
        __syncthreads();
        int n    = (bid - RA_END) * 128 + (tid >> 1);
        int half = tid & 1;                               // 0: src half, 1: dst half
        const float* wbase = sm.ws + half * 34;

        float s[8];
        #pragma unroll
        for (int k = 0; k < 8; k++) s[k] = 0.f;
        #pragma unroll
        for (int j = 0; j < 16; j++) {
            float v = a[j * NN + n];                      // 2-way broadcast, coalesced
            #pragma unroll
            for (int k = 0; k < 8; k++) s[k] += wbase[k * 68 + j] * v;
        }
        #pragma unroll
        for (int j = 0; j < 16; j++) {
            float v = u[j * NN + n];
            #pragma unroll
            for (int k = 0; k < 8; k++) s[k] += wbase[k * 68 + 16 + j] * v;
        }
        float g0 = grid[2 * n], g1 = grid[2 * n + 1];
        #pragma unroll
        for (int k = 0; k < 8; k++)
            s[k] += wbase[k * 68 + 32] * g0 + wbase[k * 68 + 33] * g1;

        float4* pv = (float4*)((half ? g_p2 : g_p1) + n * 8);
        pv[0] = make_float4(s[0], s[1], s[2], s[3]);
        pv[1] = make_float4(s[4], s[5], s[6], s[7]);
    } else if (bid < RC_END) {
        // ---- role C: out rows for b = 1..3 (root term only) ----
        int bid2 = bid - RB_END;
        int b  = 1 + (bid2 >> 6);
        int nb = (bid2 & 63) * 64;
        for (int idx = tid; idx < 32 * 32; idx += 256)
            sm.o.rs[idx >> 5][idx & 31] = root[idx];
        for (int idx = tid; idx < 64 * 32; idx += 256) {
            int i = idx >> 6, nl = idx & 63;
            int n = nb + nl;
            sm.o.xs[nl][i] = (i < 16) ? a[(b * 16 + i) * NN + n]
                                      : u[(b * 16 + (i - 16)) * NN + n];
        }
        __syncthreads();
        int og = tid >> 6, nl = tid & 63, n = nb + nl;
        #pragma unroll
        for (int oo = 0; oo < 8; oo++) {
            int o = og * 8 + oo;
            float v = 0.f;
            #pragma unroll
            for (int i = 0; i < 32; i++) v += sm.o.xs[nl][i] * sm.o.rs[i][o];
            out[(b * OUTC + o) * NN + n] = v;
        }
    } else {
        // ---- role D: zero accumulators + edge decode ----
        int t = (bid - RC_END) * 256 + tid;               // [0, 32768)
        ((float4*)g_agg)[t] = make_float4(0.f, 0.f, 0.f, 0.f);
        if (t < NN) g_cnt[t] = 0.f;

        bool is64 = true;                                 // int64 idx < 4096 -> odd words 0
        #pragma unroll
        for (int s = 1; s <= 31; s += 2) is64 = is64 && (ew[s] == 0);
        if (is64) {
            g_src[t] = ew[2 * t];
            g_dst[t] = ew[2 * NE + 2 * t];
        } else {
            g_src[t] = ew[t];
            g_dst[t] = ew[NE + t];
        }
    }
}

// ---------------------------------------------------------------------------
// Edge kernel: warp per edge. h = gelu(p1[src]+p2[dst]+b1);
// msg[o] = c[src][o] + sum_k h[k]*T[src][o*8+k]  (two LDG.128 per lane)
// ---------------------------------------------------------------------------
__global__ void __launch_bounds__(256, 8)
k_edge(const float* __restrict__ b1) {
    int gw   = (blockIdx.x * blockDim.x + threadIdx.x) >> 5;
    int lane = threadIdx.x & 31;
    int src = g_src[gw];
    int dst = g_dst[gw];

    float hv = 0.f;
    if (lane < 8) {
        float x = g_p1[src * 8 + lane] + g_p2[dst * 8 + lane] + __ldg(&b1[lane]);
        hv = 0.5f * x * (1.0f + erff(x * 0.70710678118654752f));
    }
    float h[8];
    #pragma unroll
    for (int k = 0; k < 8; k++) h[k] = __shfl_sync(0xffffffffu, hv, k);

    const float4* Tp = (const float4*)(g_T + src * 256 + lane * 8);
    float4 t0 = __ldg(Tp);
    float4 t1 = __ldg(Tp + 1);
    float m = g_c[src * 32 + lane]
            + h[0] * t0.x + h[1] * t0.y + h[2] * t0.z + h[3] * t0.w
            + h[4] * t1.x + h[5] * t1.y + h[6] * t1.z + h[7] * t1.w;

    atomicAdd(&g_agg[dst * 32 + lane], m);
    if (lane == 0) atomicAdd(&g_cnt[dst], 1.0f);
}

// ---------------------------------------------------------------------------
// Final kernel: batch-0 output (root term + agg/cnt). 64 blocks.
// ---------------------------------------------------------------------------
__global__ void k_out0(const float* __restrict__ a, const float* __restrict__ u,
                       const float* __restrict__ root, float* __restrict__ out) {
    __shared__ float xs[64][33];
    __shared__ float rs[32][32];
    int tid = threadIdx.x;
    int nb  = blockIdx.x * 64;

    for (int idx = tid; idx < 32 * 32; idx += 256)
        rs[idx >> 5][idx & 31] = root[idx];
    for (int idx = tid; idx < 64 * 32; idx += 256) {
        int i = idx >> 6, nl = idx & 63;
        int n = nb + nl;
        xs[nl][i] = (i < 16) ? a[i * NN + n] : u[(i - 16) * NN + n];
    }
    __syncthreads();

    int og = tid >> 6, nl = tid & 63, n = nb + nl;
    float inv = 1.0f / fmaxf(g_cnt[n], 1.0f);

    #pragma unroll
    for (int oo = 0; oo < 8; oo++) {
        int o = og * 8 + oo;
        float v = 0.f;
        #pragma unroll
        for (int i = 0; i < 32; i++) v += xs[nl][i] * rs[i][o];
        v += g_agg[n * 32 + o] * inv;
        out[o * NN + n] = v;
    }
}

// ---------------------------------------------------------------------------
extern "C" void kernel_launch(void* const* d_in, const int* in_sizes, int n_in,
                              void* d_out, int out_size) {
    const float* a    = (const float*)d_in[0];
    const float* u    = (const float*)d_in[1];
    const float* grid = (const float*)d_in[2];
    const int*   ew   = (const int*)  d_in[3];
    const float* w1   = (const float*)d_in[4];
    const float* b1   = (const float*)d_in[5];
    const float* w2   = (const float*)d_in[6];
    const float* b2   = (const float*)d_in[7];
    const float* root = (const float*)d_in[8];
    float* out = (float*)d_out;

    k_prep<<<RD_END, 256>>>(a, u, grid, ew, w1, w2, b2, root, out);
    k_edge<<<(NE * 32) / 256, 256>>>(b1);
    k_out0<<<64, 256>>>(a, u, root, out);
}

// round 5
// speedup vs baseline: 1.4481x; 1.0941x over previous
#include <cuda_runtime.h>
#include <math.h>

#define NB 4
#define NN 4096
#define NE 32768
#define OUTC 32
#define HID 8

// Scratch (device globals)
__device__ int   g_edge[NE];              // src | (dst<<16)
__device__ float g_p1[NN * HID];
__device__ float g_p2[NN * HID];
__device__ float g_T [NN * HID * OUTC];   // layout: T[n][o*8+k]  (4 MB)
__device__ float g_c [NN * OUTC];
__device__ float g_agg[NN * OUTC];
__device__ float g_cnt[NN];

// Role block ranges
#define RA_END 256               // T GEMM: 16 nodes/block, weights in registers
#define RB_END (RA_END + 32)     // node proj: 128 nodes/block, 2 thr/node
#define RC_END (RB_END + 192)    // out b=1..3: 64 nodes/block
#define RD_END (RC_END + 128)    // init + edge decode: 256 edges/block

// ---------------------------------------------------------------------------
// Fused prep kernel: 608 independent blocks (~1 wave @ 4 blocks/SM), 4 roles.
// ---------------------------------------------------------------------------
__global__ void __launch_bounds__(256, 4)
k_prep(const float* __restrict__ a, const float* __restrict__ u,
       const float* __restrict__ grid, const int* __restrict__ ew,
       const float* __restrict__ w1, const float* __restrict__ w2,
       const float* __restrict__ b2, const float* __restrict__ root,
       float* __restrict__ out) {
    __shared__ union {
        float xa[16 * 32];                                // role A: 16 nodes x 32 ch
        float ws[HID * 68];                               // role B
        struct { float xs[64][33]; float rs[32][32]; } o; // role C
    } sm;
    int tid = threadIdx.x;
    int bid = blockIdx.x;

    if (bid < RA_END) {
        // ---- role A: T[n][c0] = sum_i x0[n,i] * w2[i*256+c0] ----
        int nb = bid * 16;
        // weights stationary: 32 coalesced LDGs, then zero loads from global
        float w[32];
        #pragma unroll
        for (int i = 0; i < 32; i++) w[i] = __ldg(&w2[i * 256 + tid]);

        // x tile: 16 nodes x 32 ch; consecutive threads -> consecutive n
        #pragma unroll
        for (int idx = tid; idx < 512; idx += 256) {
            int i = idx >> 4, nl = idx & 15;
            sm.xa[nl * 32 + i] = (i < 16) ? a[i * NN + nb + nl]
                                          : u[(i - 16) * NN + nb + nl];
        }
        __syncthreads();

        #pragma unroll 2
        for (int nl = 0; nl < 16; nl++) {
            const float4* xv = (const float4*)(sm.xa + nl * 32);
            float acc0 = 0.f, acc1 = 0.f;
            #pragma unroll
            for (int j = 0; j < 4; j++) {
                float4 xA = xv[j];          // LDS.128 broadcast
                float4 xB = xv[j + 4];
                acc0 += xA.x * w[4*j+0] + xA.y * w[4*j+1]
                      + xA.z * w[4*j+2] + xA.w * w[4*j+3];
                acc1 += xB.x * w[16+4*j+0] + xB.y * w[16+4*j+1]
                      + xB.z * w[16+4*j+2] + xB.w * w[16+4*j+3];
            }
            g_T[(nb + nl) * 256 + tid] = acc0 + acc1;   // coalesced STG
        }

        // c[n][o] = sum_i x0[n,i]*b2[i*32+o] — 512 outputs over 256 threads
        int o = tid & 31;
        int n0 = (tid >> 5) * 2;
        #pragma unroll
        for (int hh = 0; hh < 2; hh++) {
            int nl = n0 + hh;
            float cc = 0.f;
            #pragma unroll
            for (int i = 0; i < 32; i++) cc += sm.xa[nl * 32 + i] * __ldg(&b2[i * 32 + o]);
            g_c[(nb + nl) * 32 + o] = cc;
        }
    } else if (bid < RB_END) {
        // ---- role B: node projections, 2 threads/node (half=0 -> p1, half=1 -> p2) ----
        for (int idx = tid; idx < HID * 68; idx += 256) sm.ws[idx] = w1[idx];
        __syncthreads();
        int n    = (bid - RA_END) * 128 + (tid >> 1);
        int half = tid & 1;
        const float* wbase = sm.ws + half * 34;

        float s[8];
        #pragma unroll
        for (int k = 0; k < 8; k++) s[k] = 0.f;
        #pragma unroll
        for (int j = 0; j < 16; j++) {
            float v = a[j * NN + n];
            #pragma unroll
            for (int k = 0; k < 8; k++) s[k] += wbase[k * 68 + j] * v;
        }
        #pragma unroll
        for (int j = 0; j < 16; j++) {
            float v = u[j * NN + n];
            #pragma unroll
            for (int k = 0; k < 8; k++) s[k] += wbase[k * 68 + 16 + j] * v;
        }
        float g0 = grid[2 * n], g1 = grid[2 * n + 1];
        #pragma unroll
        for (int k = 0; k < 8; k++)
            s[k] += wbase[k * 68 + 32] * g0 + wbase[k * 68 + 33] * g1;

        float4* pv = (float4*)((half ? g_p2 : g_p1) + n * 8);
        pv[0] = make_float4(s[0], s[1], s[2], s[3]);
        pv[1] = make_float4(s[4], s[5], s[6], s[7]);
    } else if (bid < RC_END) {
        // ---- role C: out rows for b = 1..3 (root term only) ----
        int bid2 = bid - RB_END;
        int b  = 1 + (bid2 >> 6);
        int nb = (bid2 & 63) * 64;
        for (int idx = tid; idx < 32 * 32; idx += 256)
            sm.o.rs[idx >> 5][idx & 31] = root[idx];
        for (int idx = tid; idx < 64 * 32; idx += 256) {
            int i = idx >> 6, nl = idx & 63;
            int n = nb + nl;
            sm.o.xs[nl][i] = (i < 16) ? a[(b * 16 + i) * NN + n]
                                      : u[(b * 16 + (i - 16)) * NN + n];
        }
        __syncthreads();
        int og = tid >> 6, nl = tid & 63, n = nb + nl;
        #pragma unroll
        for (int oo = 0; oo < 8; oo++) {
            int o = og * 8 + oo;
            float v = 0.f;
            #pragma unroll
            for (int i = 0; i < 32; i++) v += sm.o.xs[nl][i] * sm.o.rs[i][o];
            out[(b * OUTC + o) * NN + n] = v;
        }
    } else {
        // ---- role D: zero accumulators + edge decode (packed) ----
        int t = (bid - RC_END) * 256 + tid;               // [0, 32768)
        ((float4*)g_agg)[t] = make_float4(0.f, 0.f, 0.f, 0.f);
        if (t < NN) g_cnt[t] = 0.f;

        bool is64 = true;                                 // int64 idx < 4096 -> odd words 0
        #pragma unroll
        for (int s = 1; s <= 31; s += 2) is64 = is64 && (ew[s] == 0);
        int s_, d_;
        if (is64) { s_ = ew[2 * t]; d_ = ew[2 * NE + 2 * t]; }
        else      { s_ = ew[t];     d_ = ew[NE + t]; }
        g_edge[t] = s_ | (d_ << 16);
    }
}

// ---------------------------------------------------------------------------
// Edge kernel: warp per edge. h = gelu(p1[src]+p2[dst]+b1);
// msg[o] = c[src][o] + sum_k h[k]*T[src][o*8+k]  (two LDG.128 per lane)
// ---------------------------------------------------------------------------
__global__ void __launch_bounds__(256, 8)
k_edge(const float* __restrict__ b1) {
    int gw   = (blockIdx.x * blockDim.x + threadIdx.x) >> 5;
    int lane = threadIdx.x & 31;
    int e    = g_edge[gw];                 // broadcast LDG
    int src  = e & 0xFFFF;
    int dst  = e >> 16;

    float hv = 0.f;
    if (lane < 8) {
        float x = g_p1[src * 8 + lane] + g_p2[dst * 8 + lane] + __ldg(&b1[lane]);
        hv = 0.5f * x * (1.0f + erff(x * 0.70710678118654752f));
    }
    float h[8];
    #pragma unroll
    for (int k = 0; k < 8; k++) h[k] = __shfl_sync(0xffffffffu, hv, k);

    const float4* Tp = (const float4*)(g_T + src * 256 + lane * 8);
    float4 t0 = __ldg(Tp);
    float4 t1 = __ldg(Tp + 1);
    float m = g_c[src * 32 + lane]
            + h[0] * t0.x + h[1] * t0.y + h[2] * t0.z + h[3] * t0.w
            + h[4] * t1.x + h[5] * t1.y + h[6] * t1.z + h[7] * t1.w;

    atomicAdd(&g_agg[dst * 32 + lane], m);
    if (lane == 0) atomicAdd(&g_cnt[dst], 1.0f);
}

// ---------------------------------------------------------------------------
// Final kernel: batch-0 output (root term + agg/cnt). 64 blocks.
// ---------------------------------------------------------------------------
__global__ void k_out0(const float* __restrict__ a, const float* __restrict__ u,
                       const float* __restrict__ root, float* __restrict__ out) {
    __shared__ float xs[64][33];
    __shared__ float rs[32][32];
    int tid = threadIdx.x;
    int nb  = blockIdx.x * 64;

    for (int idx = tid; idx < 32 * 32; idx += 256)
        rs[idx >> 5][idx & 31] = root[idx];
    for (int idx = tid; idx < 64 * 32; idx += 256) {
        int i = idx >> 6, nl = idx & 63;
        int n = nb + nl;
        xs[nl][i] = (i < 16) ? a[i * NN + n] : u[(i - 16) * NN + n];
    }
    __syncthreads();

    int og = tid >> 6, nl = tid & 63, n = nb + nl;
    float inv = 1.0f / fmaxf(g_cnt[n], 1.0f);

    #pragma unroll
    for (int oo = 0; oo < 8; oo++) {
        int o = og * 8 + oo;
        float v = 0.f;
        #pragma unroll
        for (int i = 0; i < 32; i++) v += xs[nl][i] * rs[i][o];
        v += g_agg[n * 32 + o] * inv;
        out[o * NN + n] = v;
    }
}

// ---------------------------------------------------------------------------
extern "C" void kernel_launch(void* const* d_in, const int* in_sizes, int n_in,
                              void* d_out, int out_size) {
    const float* a    = (const float*)d_in[0];
    const float* u    = (const float*)d_in[1];
    const float* grid = (const float*)d_in[2];
    const int*   ew   = (const int*)  d_in[3];
    const float* w1   = (const float*)d_in[4];
    const float* b1   = (const float*)d_in[5];
    const float* w2   = (const float*)d_in[6];
    const float* b2   = (const float*)d_in[7];
    const float* root = (const float*)d_in[8];
    float* out = (float*)d_out;

    k_prep<<<RD_END, 256>>>(a, u, grid, ew, w1, w2, b2, root, out);
    k_edge<<<(NE * 32) / 256, 256>>>(b1);
    k_out0<<<64, 256>>>(a, u, root, out);
}